// round 8
// baseline (speedup 1.0000x reference)
#include <cuda_runtime.h>
#include <cuda_bf16.h>
#include <cstdint>

#define NSEQ 2048
#define DH   64
#define NBH  32      // B*H
#define EPSM 1.928749848e-22f   // expf(-50)

static __device__ float g_l[NBH * NSEQ];

// pack2(lo, hi): low 16 bits = bf16(lo), high = bf16(hi)
__device__ __forceinline__ uint32_t pack2(float lo, float hi) {
    uint32_t r;  // PTX: first src -> high half, second -> low half
    asm("cvt.rn.bf16x2.f32 %0, %1, %2;" : "=r"(r) : "f"(hi), "f"(lo));
    return r;
}

// portable warp-level bf16 MMA, fp32 accum (sm_80+; no 'a'-arch features)
__device__ __forceinline__ void mma16816(float* c, const uint32_t* a,
                                         uint32_t b0, uint32_t b1) {
    asm volatile(
        "mma.sync.aligned.m16n8k16.row.col.f32.bf16.bf16.f32 "
        "{%0,%1,%2,%3}, {%4,%5,%6,%7}, {%8,%9}, {%0,%1,%2,%3};"
        : "+f"(c[0]), "+f"(c[1]), "+f"(c[2]), "+f"(c[3])
        : "r"(a[0]), "r"(a[1]), "r"(a[2]), "r"(a[3]), "r"(b0), "r"(b1));
}

// ===========================================================================
// qk via mma.sync: E = exp(mask ? -50 : (q.k)/8), fused row-sum into g_l.
// CTA: 128 q x 128 k, 8 warps (4 row-bands x 2 col-halves), warp tile 32x64.
// Epilogue: direct float2 stores (32B sectors), no smem staging.
// ===========================================================================
#define KSTRIDE 72                      // bf16 units per K row (bank-safe pad)
#define SM_KHI   0
#define SM_KLO   18432
#define SM_CMASK 36864                  // 128 uchar
#define SM_LBUF  36992                  // 128 float
#define QK_SMEM  37504

__global__ void __launch_bounds__(256)
qk_mma_kernel(const float* __restrict__ q, const float* __restrict__ kmat,
              const int* __restrict__ mask, float* __restrict__ attn)
{
    __shared__ __align__(16) char smem[QK_SMEM];

    const int tid  = threadIdx.x;
    const int lane = tid & 31, wid = tid >> 5;
    const int wr = wid >> 1, wc = wid & 1;        // warp row-band / col-half
    const int g  = lane >> 2, qd = lane & 3;      // fragment group / quad
    const int qt = blockIdx.x, bh = blockIdx.y, b = bh >> 4;

    // ---- prologue: Q fragments (hi/lo) in registers for the whole kernel ----
    uint32_t aHi[2][4][4], aLo[2][4][4];
    {
        const float* qbase = q + ((size_t)bh * NSEQ + (size_t)qt * 128) * DH;
        #pragma unroll
        for (int mt = 0; mt < 2; ++mt) {
            const int r0 = wr * 32 + mt * 16 + g, r1 = r0 + 8;
            #pragma unroll
            for (int ks = 0; ks < 4; ++ks) {
                const int c0 = ks * 16 + qd * 2;
                float2 x00 = *(const float2*)(qbase + r0 * DH + c0);
                float2 x10 = *(const float2*)(qbase + r1 * DH + c0);
                float2 x01 = *(const float2*)(qbase + r0 * DH + c0 + 8);
                float2 x11 = *(const float2*)(qbase + r1 * DH + c0 + 8);
                float h, h2;
                h  = __bfloat162float(__float2bfloat16(x00.x));
                h2 = __bfloat162float(__float2bfloat16(x00.y));
                aHi[mt][ks][0] = pack2(h, h2);
                aLo[mt][ks][0] = pack2(x00.x - h, x00.y - h2);
                h  = __bfloat162float(__float2bfloat16(x10.x));
                h2 = __bfloat162float(__float2bfloat16(x10.y));
                aHi[mt][ks][1] = pack2(h, h2);
                aLo[mt][ks][1] = pack2(x10.x - h, x10.y - h2);
                h  = __bfloat162float(__float2bfloat16(x01.x));
                h2 = __bfloat162float(__float2bfloat16(x01.y));
                aHi[mt][ks][2] = pack2(h, h2);
                aLo[mt][ks][2] = pack2(x01.x - h, x01.y - h2);
                h  = __bfloat162float(__float2bfloat16(x11.x));
                h2 = __bfloat162float(__float2bfloat16(x11.y));
                aHi[mt][ks][3] = pack2(h, h2);
                aLo[mt][ks][3] = pack2(x11.x - h, x11.y - h2);
            }
        }
    }

    bool rm[2][2];
    {
        const int* mrow = mask + b * NSEQ + qt * 128;
        #pragma unroll
        for (int mt = 0; mt < 2; ++mt) {
            rm[mt][0] = mrow[wr * 32 + mt * 16 + g] != 0;
            rm[mt][1] = mrow[wr * 32 + mt * 16 + g + 8] != 0;
        }
    }

    float lsum[2][2] = {{0.f, 0.f}, {0.f, 0.f}};
    unsigned char* cmaskA = (unsigned char*)(smem + SM_CMASK);
    float* abase = attn + ((size_t)bh * NSEQ + (size_t)qt * 128) * NSEQ;
    const float* kball = kmat + (size_t)bh * NSEQ * DH;

    for (int kt = 0; kt < NSEQ / 128; ++kt) {
        __syncthreads();   // MMA of prev chunk done reading Ks/cmask

        // ---- K chunk: 128 k-rows x 64 d, fp32 -> hi/lo bf16 smem ----
        {
            const int r  = tid >> 1;
            const int cc = (tid & 1) * 32;
            const float* kb = kball + (size_t)(kt * 128 + r) * DH + cc;
            char* hB = smem + SM_KHI + (size_t)r * (KSTRIDE * 2);
            char* lB = smem + SM_KLO + (size_t)r * (KSTRIDE * 2);
            #pragma unroll
            for (int c4 = 0; c4 < 32; c4 += 4) {
                float4 x = *(const float4*)(kb + c4);
                float h0 = __bfloat162float(__float2bfloat16(x.x));
                float h1 = __bfloat162float(__float2bfloat16(x.y));
                float h2 = __bfloat162float(__float2bfloat16(x.z));
                float h3 = __bfloat162float(__float2bfloat16(x.w));
                *(uint32_t*)(hB + (cc + c4) * 2)     = pack2(h0, h1);
                *(uint32_t*)(hB + (cc + c4 + 2) * 2) = pack2(h2, h3);
                *(uint32_t*)(lB + (cc + c4) * 2)     = pack2(x.x - h0, x.y - h1);
                *(uint32_t*)(lB + (cc + c4 + 2) * 2) = pack2(x.z - h2, x.w - h3);
            }
        }
        if (tid < 128)
            cmaskA[tid] = (unsigned char)(mask[b * NSEQ + kt * 128 + tid] != 0);
        __syncthreads();

        // ---- MMA: 8 n-tiles x 4 k-steps x 3 products x 2 m-tiles ----
        float acc[2][8][4];
        #pragma unroll
        for (int mt = 0; mt < 2; ++mt)
            #pragma unroll
            for (int nt = 0; nt < 8; ++nt)
                #pragma unroll
                for (int u = 0; u < 4; ++u) acc[mt][nt][u] = 0.f;

        #pragma unroll
        for (int nt = 0; nt < 8; ++nt) {
            const int nrow = wc * 64 + nt * 8 + g;
            const char* krH = smem + SM_KHI + (size_t)nrow * (KSTRIDE * 2);
            const char* krL = smem + SM_KLO + (size_t)nrow * (KSTRIDE * 2);
            #pragma unroll
            for (int ks = 0; ks < 4; ++ks) {
                const int koff = (ks * 16 + qd * 2) * 2;
                uint32_t bh0 = *(const uint32_t*)(krH + koff);
                uint32_t bh1 = *(const uint32_t*)(krH + koff + 16);
                uint32_t bl0 = *(const uint32_t*)(krL + koff);
                uint32_t bl1 = *(const uint32_t*)(krL + koff + 16);
                #pragma unroll
                for (int mt = 0; mt < 2; ++mt) {
                    mma16816(acc[mt][nt], aHi[mt][ks], bh0, bh1);
                    mma16816(acc[mt][nt], aHi[mt][ks], bl0, bl1);
                    mma16816(acc[mt][nt], aLo[mt][ks], bh0, bh1);
                }
            }
        }

        // ---- epilogue: exp + mask + row-sum + direct float2 stores ----
        #pragma unroll
        for (int mt = 0; mt < 2; ++mt) {
            const int r0 = wr * 32 + mt * 16 + g;
            #pragma unroll
            for (int nt = 0; nt < 8; ++nt) {
                const int col0 = nt * 8 + qd * 2;
                const uint16_t mm = *(const uint16_t*)(cmaskA + wc * 64 + col0);
                const bool m0 = (mm & 0xffu) != 0, m1 = (mm >> 8) != 0;
                float* c = acc[mt][nt];
                float e0 = (rm[mt][0] || m0) ? EPSM : __expf(c[0] * 0.125f);
                float e1 = (rm[mt][0] || m1) ? EPSM : __expf(c[1] * 0.125f);
                float e2 = (rm[mt][1] || m0) ? EPSM : __expf(c[2] * 0.125f);
                float e3 = (rm[mt][1] || m1) ? EPSM : __expf(c[3] * 0.125f);
                lsum[mt][0] += e0 + e1;
                lsum[mt][1] += e2 + e3;
                float* dst = abase + (size_t)r0 * NSEQ + kt * 128 + wc * 64 + col0;
                *(float2*)dst = make_float2(e0, e1);
                *(float2*)(dst + 8 * NSEQ) = make_float2(e2, e3);
            }
        }
    }

    // ---- final row-sum reduce: quad shfl, then combine the two col-halves ----
    #pragma unroll
    for (int mt = 0; mt < 2; ++mt)
        #pragma unroll
        for (int h = 0; h < 2; ++h) {
            float s = lsum[mt][h];
            s += __shfl_xor_sync(0xffffffffu, s, 1);
            s += __shfl_xor_sync(0xffffffffu, s, 2);
            lsum[mt][h] = s;
        }
    float* lbuf = (float*)(smem + SM_LBUF);
    __syncthreads();
    if (wc == 1 && qd == 0) {
        #pragma unroll
        for (int mt = 0; mt < 2; ++mt) {
            lbuf[wr * 32 + mt * 16 + g]     = lsum[mt][0];
            lbuf[wr * 32 + mt * 16 + g + 8] = lsum[mt][1];
        }
    }
    __syncthreads();
    if (wc == 0 && qd == 0) {
        #pragma unroll
        for (int mt = 0; mt < 2; ++mt) {
            const int r0 = wr * 32 + mt * 16 + g;
            g_l[bh * NSEQ + qt * 128 + r0]     = lsum[mt][0] + lbuf[r0];
            g_l[bh * NSEQ + qt * 128 + r0 + 8] = lsum[mt][1] + lbuf[r0 + 8];
        }
    }
}

// ===========================================================================
// pv via mma.sync: p = E/l (written back as attn), O = P.V (bf16 hi/lo split).
// CTA: 128 q-rows x 64 d, 256 threads = 8 warps of 16 exclusive rows.
// E loaded gmem->regs in A-fragment layout (no smem for P). V transposed
// bf16 hi/lo in smem (stride 136 -> conflict-free B reads).
// ===========================================================================
#define VT_STRIDE 136                 // bf16 units per Vt row (d-major)
#define PV_VHI 0
#define PV_VLO 17408
#define PV_SMEM 34816

__global__ void __launch_bounds__(256)
pv_mma_kernel(const float* __restrict__ v, float* __restrict__ attn,
              float* __restrict__ out)
{
    __shared__ __align__(16) char smem[PV_SMEM];

    const int tid  = threadIdx.x;
    const int lane = tid & 31, wid = tid >> 5;     // warp = 16-row band
    const int g = lane >> 2, qd = lane & 3;
    const int qt = blockIdx.x, bh = blockIdx.y;

    const int r0 = wid * 16 + g;                   // this thread's rows: r0, r0+8
    const float rl0 = 1.f / g_l[bh * NSEQ + qt * 128 + r0];
    const float rl1 = 1.f / g_l[bh * NSEQ + qt * 128 + r0 + 8];

    float* abase = attn + ((size_t)bh * NSEQ + (size_t)qt * 128) * NSEQ;
    const float* vbase = v + (size_t)bh * NSEQ * DH;

    float acc[8][4];
    #pragma unroll
    for (int nt = 0; nt < 8; ++nt)
        #pragma unroll
        for (int u = 0; u < 4; ++u) acc[nt][u] = 0.f;

    for (int kt = 0; kt < NSEQ / 128; ++kt) {
        __syncthreads();   // prev chunk MMA done reading Vt

        // ---- V chunk 128k x 64d -> transposed bf16 hi/lo smem ----
        {
            const int kr = tid >> 1;               // 0..127 (k within chunk)
            const int c0 = (tid & 1) * 32;         // d base
            const float* vb = vbase + (size_t)(kt * 128 + kr) * DH + c0;
            uint16_t* vh = (uint16_t*)(smem + PV_VHI);
            uint16_t* vl = (uint16_t*)(smem + PV_VLO);
            #pragma unroll
            for (int c4 = 0; c4 < 32; c4 += 4) {
                float4 x = *(const float4*)(vb + c4);
                float xa[4] = {x.x, x.y, x.z, x.w};
                #pragma unroll
                for (int u = 0; u < 4; ++u) {
                    const int d = c0 + c4 + u;
                    __nv_bfloat16 hb = __float2bfloat16(xa[u]);
                    float h = __bfloat162float(hb);
                    vh[d * VT_STRIDE + kr] = __bfloat16_as_ushort(hb);
                    vl[d * VT_STRIDE + kr] =
                        __bfloat16_as_ushort(__float2bfloat16(xa[u] - h));
                }
            }
        }
        __syncthreads();

        // ---- 8 k-steps of 16: E->P in fragment layout, then MMA over 8 nt ----
        // prefetch ks=0 E fragments
        float2 e00, e10, e01, e11;
        {
            const float* ep = abase + (size_t)r0 * NSEQ + kt * 128 + qd * 2;
            e00 = *(const float2*)(ep);
            e10 = *(const float2*)(ep + 8 * NSEQ);
            e01 = *(const float2*)(ep + 8);
            e11 = *(const float2*)(ep + 8 * NSEQ + 8);
        }

        #pragma unroll
        for (int ks = 0; ks < 8; ++ks) {
            // normalize, write P back, build hi/lo A fragments
            float p00x = e00.x * rl0, p00y = e00.y * rl0;
            float p10x = e10.x * rl1, p10y = e10.y * rl1;
            float p01x = e01.x * rl0, p01y = e01.y * rl0;
            float p11x = e11.x * rl1, p11y = e11.y * rl1;
            {
                float* pp = abase + (size_t)r0 * NSEQ + kt * 128 + ks * 16 + qd * 2;
                *(float2*)(pp)                = make_float2(p00x, p00y);
                *(float2*)(pp + 8 * NSEQ)     = make_float2(p10x, p10y);
                *(float2*)(pp + 8)            = make_float2(p01x, p01y);
                *(float2*)(pp + 8 * NSEQ + 8) = make_float2(p11x, p11y);
            }
            uint32_t pHi[4], pLo[4];
            {
                float h, h2;
                h  = __bfloat162float(__float2bfloat16(p00x));
                h2 = __bfloat162float(__float2bfloat16(p00y));
                pHi[0] = pack2(h, h2); pLo[0] = pack2(p00x - h, p00y - h2);
                h  = __bfloat162float(__float2bfloat16(p10x));
                h2 = __bfloat162float(__float2bfloat16(p10y));
                pHi[1] = pack2(h, h2); pLo[1] = pack2(p10x - h, p10y - h2);
                h  = __bfloat162float(__float2bfloat16(p01x));
                h2 = __bfloat162float(__float2bfloat16(p01y));
                pHi[2] = pack2(h, h2); pLo[2] = pack2(p01x - h, p01y - h2);
                h  = __bfloat162float(__float2bfloat16(p11x));
                h2 = __bfloat162float(__float2bfloat16(p11y));
                pHi[3] = pack2(h, h2); pLo[3] = pack2(p11x - h, p11y - h2);
            }

            // prefetch next ks E fragments (overlaps the MMAs below)
            if (ks + 1 < 8) {
                const float* ep = abase + (size_t)r0 * NSEQ + kt * 128
                                + (ks + 1) * 16 + qd * 2;
                e00 = *(const float2*)(ep);
                e10 = *(const float2*)(ep + 8 * NSEQ);
                e01 = *(const float2*)(ep + 8);
                e11 = *(const float2*)(ep + 8 * NSEQ + 8);
            }

            const uint32_t* vh32 = (const uint32_t*)(smem + PV_VHI);
            const uint32_t* vl32 = (const uint32_t*)(smem + PV_VLO);
            const int kw = ks * 8 + qd;            // word offset within Vt row
            #pragma unroll
            for (int nt = 0; nt < 8; ++nt) {
                const int base = (nt * 8 + g) * (VT_STRIDE / 2) + kw;
                uint32_t bh0 = vh32[base], bh1 = vh32[base + 4];
                uint32_t bl0 = vl32[base], bl1 = vl32[base + 4];
                mma16816(acc[nt], pHi, bh0, bh1);
                mma16816(acc[nt], pHi, bl0, bl1);
                mma16816(acc[nt], pLo, bh0, bh1);
            }
        }
    }

    // ---- O stores ----
    float* obase = out + ((size_t)bh * NSEQ + (size_t)qt * 128) * DH;
    #pragma unroll
    for (int nt = 0; nt < 8; ++nt) {
        float* op = obase + (size_t)r0 * DH + nt * 8 + qd * 2;
        *(float2*)op            = make_float2(acc[nt][0], acc[nt][1]);
        *(float2*)(op + 8 * DH) = make_float2(acc[nt][2], acc[nt][3]);
    }
}

extern "C" void kernel_launch(void* const* d_in, const int* in_sizes, int n_in,
                              void* d_out, int out_size)
{
    const float* q    = (const float*)d_in[0];
    const float* kmat = (const float*)d_in[1];
    const float* v    = (const float*)d_in[2];
    const int*   mask = (const int*)d_in[3];

    float* out  = (float*)d_out;                  // [B,H,N,D] first (tuple order)
    float* attn = out + (size_t)NBH * NSEQ * DH;  // [B,H,N,N] second

    qk_mma_kernel<<<dim3(NSEQ / 128, NBH), 256>>>(q, kmat, mask, attn);
    pv_mma_kernel<<<dim3(NSEQ / 128, NBH), 256>>>(v, attn, out);
}

// round 10
// speedup vs baseline: 2.1442x; 2.1442x over previous
#include <cuda_runtime.h>
#include <cuda_bf16.h>
#include <cstdint>

#define NSEQ 2048
#define DH   64
#define NBH  32      // B*H
#define EPSM 1.928749848e-22f   // expf(-50)

static __device__ float g_l[NBH * NSEQ];

// pack2(lo, hi): low 16 bits = bf16(lo), high = bf16(hi)
__device__ __forceinline__ uint32_t pack2(float lo, float hi) {
    uint32_t r;  // PTX: first src -> high half, second -> low half
    asm("cvt.rn.bf16x2.f32 %0, %1, %2;" : "=r"(r) : "f"(hi), "f"(lo));
    return r;
}

// portable warp-level bf16 MMA, fp32 accum (sm_80+; no 'a'-arch features)
__device__ __forceinline__ void mma16816(float* c, const uint32_t* a,
                                         uint32_t b0, uint32_t b1) {
    asm volatile(
        "mma.sync.aligned.m16n8k16.row.col.f32.bf16.bf16.f32 "
        "{%0,%1,%2,%3}, {%4,%5,%6,%7}, {%8,%9}, {%0,%1,%2,%3};"
        : "+f"(c[0]), "+f"(c[1]), "+f"(c[2]), "+f"(c[3])
        : "r"(a[0]), "r"(a[1]), "r"(a[2]), "r"(a[3]), "r"(b0), "r"(b1));
}

// ===========================================================================
// qk via mma.sync, pipelined: E = exp(mask ? -50 : (q.k)/8), row-sum -> g_l.
// CTA: 128 q-rows, 8 warps = 8 exclusive 16-row bands, full 64-col K chunks.
// Next K chunk (+mask) register-prefetched while current chunk's MMAs run.
// ===========================================================================
#define KT 64                          // k-rows per chunk
#define KROW_B 144                     // bytes per K smem row (72 bf16, padded)
#define SM_KHI   0                     // 64*144 = 9216
#define SM_KLO   9216                  // 9216
#define SM_CMASK 18432                 // 64 uchar
#define QK_SMEM  18560

__global__ void __launch_bounds__(256, 2)
qk_mma_kernel(const float* __restrict__ q, const float* __restrict__ kmat,
              const int* __restrict__ mask, float* __restrict__ attn)
{
    __shared__ __align__(16) char smem[QK_SMEM];

    const int tid  = threadIdx.x;
    const int lane = tid & 31, wid = tid >> 5;
    const int g  = lane >> 2, qd = lane & 3;      // fragment group / quad
    const int qt = blockIdx.x, bh = blockIdx.y, b = bh >> 4;

    // ---- prologue: Q fragments (hi/lo) in registers for the whole kernel ----
    // warp rows: r0 = wid*16+g, r1 = r0+8
    uint32_t aHi[4][4], aLo[4][4];
    const int r0 = wid * 16 + g;
    {
        const float* qbase = q + ((size_t)bh * NSEQ + (size_t)qt * 128) * DH;
        #pragma unroll
        for (int ks = 0; ks < 4; ++ks) {
            const int c0 = ks * 16 + qd * 2;
            float2 x00 = *(const float2*)(qbase + r0 * DH + c0);
            float2 x10 = *(const float2*)(qbase + (r0 + 8) * DH + c0);
            float2 x01 = *(const float2*)(qbase + r0 * DH + c0 + 8);
            float2 x11 = *(const float2*)(qbase + (r0 + 8) * DH + c0 + 8);
            float h, h2;
            h  = __bfloat162float(__float2bfloat16(x00.x));
            h2 = __bfloat162float(__float2bfloat16(x00.y));
            aHi[ks][0] = pack2(h, h2);
            aLo[ks][0] = pack2(x00.x - h, x00.y - h2);
            h  = __bfloat162float(__float2bfloat16(x10.x));
            h2 = __bfloat162float(__float2bfloat16(x10.y));
            aHi[ks][1] = pack2(h, h2);
            aLo[ks][1] = pack2(x10.x - h, x10.y - h2);
            h  = __bfloat162float(__float2bfloat16(x01.x));
            h2 = __bfloat162float(__float2bfloat16(x01.y));
            aHi[ks][2] = pack2(h, h2);
            aLo[ks][2] = pack2(x01.x - h, x01.y - h2);
            h  = __bfloat162float(__float2bfloat16(x11.x));
            h2 = __bfloat162float(__float2bfloat16(x11.y));
            aHi[ks][3] = pack2(h, h2);
            aLo[ks][3] = pack2(x11.x - h, x11.y - h2);
        }
    }

    const bool rm0 = mask[b * NSEQ + qt * 128 + r0] != 0;
    const bool rm1 = mask[b * NSEQ + qt * 128 + r0 + 8] != 0;
    float lsum0 = 0.f, lsum1 = 0.f;

    unsigned char* cmaskA = (unsigned char*)(smem + SM_CMASK);
    float* abase = attn + ((size_t)bh * NSEQ + (size_t)qt * 128) * NSEQ;
    const float* kball = kmat + (size_t)bh * NSEQ * DH;

    // K prefetch mapping: r = tid>>2 (0..63), c0 = (tid&3)*16
    const int kr  = tid >> 2;
    const int kc0 = (tid & 3) * 16;
    float4 kReg[4];
    int    mreg = 0;
    {
        const float* kb = kball + (size_t)kr * DH + kc0;
        #pragma unroll
        for (int u = 0; u < 4; ++u) kReg[u] = *(const float4*)(kb + 4 * u);
        if (tid < KT) mreg = mask[b * NSEQ + tid];
    }

    for (int kt = 0; kt < NSEQ / KT; ++kt) {
        __syncthreads();   // all warps done with prev chunk's smem

        // ---- commit prefetched K chunk: hi/lo split -> packed 32-bit STS ----
        {
            char* hB = smem + SM_KHI + (size_t)kr * KROW_B;
            char* lB = smem + SM_KLO + (size_t)kr * KROW_B;
            #pragma unroll
            for (int u4 = 0; u4 < 4; ++u4) {
                float4 x = kReg[u4];
                float h0 = __bfloat162float(__float2bfloat16(x.x));
                float h1 = __bfloat162float(__float2bfloat16(x.y));
                float h2 = __bfloat162float(__float2bfloat16(x.z));
                float h3 = __bfloat162float(__float2bfloat16(x.w));
                const int c = kc0 + u4 * 4;
                *(uint32_t*)(hB + c * 2)       = pack2(h0, h1);
                *(uint32_t*)(hB + (c + 2) * 2) = pack2(h2, h3);
                *(uint32_t*)(lB + c * 2)       = pack2(x.x - h0, x.y - h1);
                *(uint32_t*)(lB + (c + 2) * 2) = pack2(x.z - h2, x.w - h3);
            }
            if (tid < KT) cmaskA[tid] = (unsigned char)(mreg != 0);
        }
        __syncthreads();

        // ---- prefetch next chunk into registers (consumed next iteration) ----
        {
            const int nkt = (kt + 1 < NSEQ / KT) ? kt + 1 : kt;
            const float* kb = kball + (size_t)(nkt * KT + kr) * DH + kc0;
            #pragma unroll
            for (int u = 0; u < 4; ++u) kReg[u] = *(const float4*)(kb + 4 * u);
            if (tid < KT) mreg = mask[b * NSEQ + nkt * KT + tid];
        }

        // ---- MMA: 8 n-tiles x 4 k-steps x 3 products ----
        float acc[8][4];
        #pragma unroll
        for (int nt = 0; nt < 8; ++nt)
            #pragma unroll
            for (int u = 0; u < 4; ++u) acc[nt][u] = 0.f;

        #pragma unroll
        for (int nt = 0; nt < 8; ++nt) {
            const int nrow = nt * 8 + g;
            const char* krH = smem + SM_KHI + (size_t)nrow * KROW_B;
            const char* krL = smem + SM_KLO + (size_t)nrow * KROW_B;
            #pragma unroll
            for (int ks = 0; ks < 4; ++ks) {
                const int koff = (ks * 16 + qd * 2) * 2;
                uint32_t bh0 = *(const uint32_t*)(krH + koff);
                uint32_t bh1 = *(const uint32_t*)(krH + koff + 16);
                uint32_t bl0 = *(const uint32_t*)(krL + koff);
                uint32_t bl1 = *(const uint32_t*)(krL + koff + 16);
                mma16816(acc[nt], aHi[ks], bh0, bh1);
                mma16816(acc[nt], aHi[ks], bl0, bl1);
                mma16816(acc[nt], aLo[ks], bh0, bh1);
            }
        }

        // ---- epilogue: exp + mask + row-sum + direct float2 stores ----
        #pragma unroll
        for (int nt = 0; nt < 8; ++nt) {
            const int col0 = nt * 8 + qd * 2;
            const uint16_t mm = *(const uint16_t*)(cmaskA + col0);
            const bool m0 = (mm & 0xffu) != 0, m1 = (mm >> 8) != 0;
            float* c = acc[nt];
            float e0 = (rm0 || m0) ? EPSM : __expf(c[0] * 0.125f);
            float e1 = (rm0 || m1) ? EPSM : __expf(c[1] * 0.125f);
            float e2 = (rm1 || m0) ? EPSM : __expf(c[2] * 0.125f);
            float e3 = (rm1 || m1) ? EPSM : __expf(c[3] * 0.125f);
            lsum0 += e0 + e1;
            lsum1 += e2 + e3;
            float* dst = abase + (size_t)r0 * NSEQ + kt * KT + col0;
            *(float2*)dst              = make_float2(e0, e1);
            *(float2*)(dst + 8 * NSEQ) = make_float2(e2, e3);
        }
    }

    // ---- row-sum reduce across the 4 quads; rows are warp-exclusive ----
    lsum0 += __shfl_xor_sync(0xffffffffu, lsum0, 1);
    lsum0 += __shfl_xor_sync(0xffffffffu, lsum0, 2);
    lsum1 += __shfl_xor_sync(0xffffffffu, lsum1, 1);
    lsum1 += __shfl_xor_sync(0xffffffffu, lsum1, 2);
    if (qd == 0) {
        g_l[bh * NSEQ + qt * 128 + r0]     = lsum0;
        g_l[bh * NSEQ + qt * 128 + r0 + 8] = lsum1;
    }
}

// ---------------------------------------------------------------------------
// pv (scalar, round-4, known 435us): p = E/l (written back as attn), O = P.V
// ---------------------------------------------------------------------------
__global__ __launch_bounds__(128) void pv_kernel(
    const float* __restrict__ v, float* __restrict__ attn,
    float* __restrict__ out)
{
    __shared__ float Ps[128 * 36];
    __shared__ float Vs[32 * 68];

    const int qt  = blockIdx.x;
    const int bh  = blockIdx.y;
    const int tid = threadIdx.x;
    const int tx  = tid & 7;
    const int ty  = tid >> 3;

    const int sc  = (tid & 7) * 4;
    const int sr0 = tid >> 3;
    const int vr  = tid >> 2;
    const int vc  = (tid & 3) * 16;

    float rlv[8];
    #pragma unroll
    for (int i = 0; i < 8; ++i)
        rlv[i] = 1.f / g_l[bh * NSEQ + qt * 128 + sr0 + 16 * i];

    float* abase = attn + ((size_t)bh * NSEQ + (size_t)qt * 128) * NSEQ;
    const float* vbase = v + (size_t)bh * NSEQ * DH;

    float4 eReg[8];
    float4 vReg[4];
    #pragma unroll
    for (int i = 0; i < 8; ++i)
        eReg[i] = *(const float4*)(abase + (size_t)(sr0 + 16 * i) * NSEQ + sc);
    #pragma unroll
    for (int j = 0; j < 4; ++j)
        vReg[j] = *(const float4*)(vbase + (size_t)vr * DH + vc + 4 * j);

    float acc[8][8];
    #pragma unroll
    for (int i = 0; i < 8; ++i)
        #pragma unroll
        for (int j = 0; j < 8; ++j) acc[i][j] = 0.f;

    for (int kt = 0; kt < NSEQ / 32; ++kt) {
        __syncthreads();
        #pragma unroll
        for (int i = 0; i < 8; ++i) {
            const int r = sr0 + 16 * i;
            const float s = rlv[i];
            float4 p4 = make_float4(eReg[i].x * s, eReg[i].y * s,
                                    eReg[i].z * s, eReg[i].w * s);
            *(float4*)(abase + (size_t)r * NSEQ + kt * 32 + sc) = p4;
            *(float4*)&Ps[r * 36 + sc] = p4;
        }
        #pragma unroll
        for (int j = 0; j < 4; ++j)
            *(float4*)&Vs[vr * 68 + vc + 4 * j] = vReg[j];
        __syncthreads();

        if (kt + 1 < NSEQ / 32) {
            const float* ebp = abase + (kt + 1) * 32 + sc;
            #pragma unroll
            for (int i = 0; i < 8; ++i)
                eReg[i] = *(const float4*)(ebp + (size_t)(sr0 + 16 * i) * NSEQ);
            const float* vbp = vbase + (size_t)((kt + 1) * 32 + vr) * DH + vc;
            #pragma unroll
            for (int j = 0; j < 4; ++j)
                vReg[j] = *(const float4*)(vbp + 4 * j);
        }

        #pragma unroll
        for (int k0 = 0; k0 < 32; k0 += 4) {
            float Pfa[8][4];
            #pragma unroll
            for (int i = 0; i < 8; ++i) {
                const int r = ((i >> 2) * 64) + ty * 4 + (i & 3);
                float4 t = *(const float4*)&Ps[r * 36 + k0];
                Pfa[i][0] = t.x; Pfa[i][1] = t.y; Pfa[i][2] = t.z; Pfa[i][3] = t.w;
            }
            #pragma unroll
            for (int kk = 0; kk < 4; ++kk) {
                float4 v0 = *(const float4*)&Vs[(k0 + kk) * 68 + tx * 4];
                float4 v1 = *(const float4*)&Vs[(k0 + kk) * 68 + 32 + tx * 4];
                float bv[8] = {v0.x, v0.y, v0.z, v0.w, v1.x, v1.y, v1.z, v1.w};
                #pragma unroll
                for (int i = 0; i < 8; ++i)
                    #pragma unroll
                    for (int j = 0; j < 8; ++j)
                        acc[i][j] += Pfa[i][kk] * bv[j];
            }
        }
    }

    float* obase = out + ((size_t)bh * NSEQ + (size_t)qt * 128) * DH;
    #pragma unroll
    for (int i = 0; i < 8; ++i) {
        const int row = ((i >> 2) * 64) + ty * 4 + (i & 3);
        *(float4*)(obase + (size_t)row * DH + tx * 4)
            = make_float4(acc[i][0], acc[i][1], acc[i][2], acc[i][3]);
        *(float4*)(obase + (size_t)row * DH + 32 + tx * 4)
            = make_float4(acc[i][4], acc[i][5], acc[i][6], acc[i][7]);
    }
}

extern "C" void kernel_launch(void* const* d_in, const int* in_sizes, int n_in,
                              void* d_out, int out_size)
{
    const float* q    = (const float*)d_in[0];
    const float* kmat = (const float*)d_in[1];
    const float* v    = (const float*)d_in[2];
    const int*   mask = (const int*)d_in[3];

    float* out  = (float*)d_out;                  // [B,H,N,D] first (tuple order)
    float* attn = out + (size_t)NBH * NSEQ * DH;  // [B,H,N,N] second

    qk_mma_kernel<<<dim3(NSEQ / 128, NBH), 256>>>(q, kmat, mask, attn);
    pv_kernel<<<dim3(NSEQ / 128, NBH), 128>>>(v, attn, out);
}

// round 11
// speedup vs baseline: 2.6305x; 1.2268x over previous
#include <cuda_runtime.h>
#include <cuda_bf16.h>
#include <cstdint>

#define NSEQ 2048
#define DH   64
#define NBH  32      // B*H
#define EPSM 1.928749848e-22f   // expf(-50)

static __device__ float g_l[NBH * NSEQ];

// pack2(lo, hi): low 16 bits = bf16(lo), high = bf16(hi)
__device__ __forceinline__ uint32_t pack2(float lo, float hi) {
    uint32_t r;  // PTX: first src -> high half, second -> low half
    asm("cvt.rn.bf16x2.f32 %0, %1, %2;" : "=r"(r) : "f"(hi), "f"(lo));
    return r;
}

// portable warp-level bf16 MMA, fp32 accum (sm_80+; no 'a'-arch features)
__device__ __forceinline__ void mma16816(float* c, const uint32_t* a,
                                         uint32_t b0, uint32_t b1) {
    asm volatile(
        "mma.sync.aligned.m16n8k16.row.col.f32.bf16.bf16.f32 "
        "{%0,%1,%2,%3}, {%4,%5,%6,%7}, {%8,%9}, {%0,%1,%2,%3};"
        : "+f"(c[0]), "+f"(c[1]), "+f"(c[2]), "+f"(c[3])
        : "r"(a[0]), "r"(a[1]), "r"(a[2]), "r"(a[3]), "r"(b0), "r"(b1));
}

// ===========================================================================
// qk via mma.sync, pipelined (R10, 272us): E = exp(mask ? -50 : (q.k)/8).
// ===========================================================================
#define KT 64                          // k-rows per chunk
#define KROW_B 144                     // bytes per K smem row (72 bf16, padded)
#define SM_KHI   0
#define SM_KLO   9216
#define SM_CMASK 18432
#define QK_SMEM  18560

__global__ void __launch_bounds__(256, 2)
qk_mma_kernel(const float* __restrict__ q, const float* __restrict__ kmat,
              const int* __restrict__ mask, float* __restrict__ attn)
{
    __shared__ __align__(16) char smem[QK_SMEM];

    const int tid  = threadIdx.x;
    const int lane = tid & 31, wid = tid >> 5;
    const int g  = lane >> 2, qd = lane & 3;
    const int qt = blockIdx.x, bh = blockIdx.y, b = bh >> 4;

    uint32_t aHi[4][4], aLo[4][4];
    const int r0 = wid * 16 + g;
    {
        const float* qbase = q + ((size_t)bh * NSEQ + (size_t)qt * 128) * DH;
        #pragma unroll
        for (int ks = 0; ks < 4; ++ks) {
            const int c0 = ks * 16 + qd * 2;
            float2 x00 = *(const float2*)(qbase + r0 * DH + c0);
            float2 x10 = *(const float2*)(qbase + (r0 + 8) * DH + c0);
            float2 x01 = *(const float2*)(qbase + r0 * DH + c0 + 8);
            float2 x11 = *(const float2*)(qbase + (r0 + 8) * DH + c0 + 8);
            float h, h2;
            h  = __bfloat162float(__float2bfloat16(x00.x));
            h2 = __bfloat162float(__float2bfloat16(x00.y));
            aHi[ks][0] = pack2(h, h2);
            aLo[ks][0] = pack2(x00.x - h, x00.y - h2);
            h  = __bfloat162float(__float2bfloat16(x10.x));
            h2 = __bfloat162float(__float2bfloat16(x10.y));
            aHi[ks][1] = pack2(h, h2);
            aLo[ks][1] = pack2(x10.x - h, x10.y - h2);
            h  = __bfloat162float(__float2bfloat16(x01.x));
            h2 = __bfloat162float(__float2bfloat16(x01.y));
            aHi[ks][2] = pack2(h, h2);
            aLo[ks][2] = pack2(x01.x - h, x01.y - h2);
            h  = __bfloat162float(__float2bfloat16(x11.x));
            h2 = __bfloat162float(__float2bfloat16(x11.y));
            aHi[ks][3] = pack2(h, h2);
            aLo[ks][3] = pack2(x11.x - h, x11.y - h2);
        }
    }

    const bool rm0 = mask[b * NSEQ + qt * 128 + r0] != 0;
    const bool rm1 = mask[b * NSEQ + qt * 128 + r0 + 8] != 0;
    float lsum0 = 0.f, lsum1 = 0.f;

    unsigned char* cmaskA = (unsigned char*)(smem + SM_CMASK);
    float* abase = attn + ((size_t)bh * NSEQ + (size_t)qt * 128) * NSEQ;
    const float* kball = kmat + (size_t)bh * NSEQ * DH;

    const int kr  = tid >> 2;
    const int kc0 = (tid & 3) * 16;
    float4 kReg[4];
    int    mreg = 0;
    {
        const float* kb = kball + (size_t)kr * DH + kc0;
        #pragma unroll
        for (int u = 0; u < 4; ++u) kReg[u] = *(const float4*)(kb + 4 * u);
        if (tid < KT) mreg = mask[b * NSEQ + tid];
    }

    for (int kt = 0; kt < NSEQ / KT; ++kt) {
        __syncthreads();

        {
            char* hB = smem + SM_KHI + (size_t)kr * KROW_B;
            char* lB = smem + SM_KLO + (size_t)kr * KROW_B;
            #pragma unroll
            for (int u4 = 0; u4 < 4; ++u4) {
                float4 x = kReg[u4];
                float h0 = __bfloat162float(__float2bfloat16(x.x));
                float h1 = __bfloat162float(__float2bfloat16(x.y));
                float h2 = __bfloat162float(__float2bfloat16(x.z));
                float h3 = __bfloat162float(__float2bfloat16(x.w));
                const int c = kc0 + u4 * 4;
                *(uint32_t*)(hB + c * 2)       = pack2(h0, h1);
                *(uint32_t*)(hB + (c + 2) * 2) = pack2(h2, h3);
                *(uint32_t*)(lB + c * 2)       = pack2(x.x - h0, x.y - h1);
                *(uint32_t*)(lB + (c + 2) * 2) = pack2(x.z - h2, x.w - h3);
            }
            if (tid < KT) cmaskA[tid] = (unsigned char)(mreg != 0);
        }
        __syncthreads();

        {
            const int nkt = (kt + 1 < NSEQ / KT) ? kt + 1 : kt;
            const float* kb = kball + (size_t)(nkt * KT + kr) * DH + kc0;
            #pragma unroll
            for (int u = 0; u < 4; ++u) kReg[u] = *(const float4*)(kb + 4 * u);
            if (tid < KT) mreg = mask[b * NSEQ + nkt * KT + tid];
        }

        float acc[8][4];
        #pragma unroll
        for (int nt = 0; nt < 8; ++nt)
            #pragma unroll
            for (int u = 0; u < 4; ++u) acc[nt][u] = 0.f;

        #pragma unroll
        for (int nt = 0; nt < 8; ++nt) {
            const int nrow = nt * 8 + g;
            const char* krH = smem + SM_KHI + (size_t)nrow * KROW_B;
            const char* krL = smem + SM_KLO + (size_t)nrow * KROW_B;
            #pragma unroll
            for (int ks = 0; ks < 4; ++ks) {
                const int koff = (ks * 16 + qd * 2) * 2;
                uint32_t bh0 = *(const uint32_t*)(krH + koff);
                uint32_t bh1 = *(const uint32_t*)(krH + koff + 16);
                uint32_t bl0 = *(const uint32_t*)(krL + koff);
                uint32_t bl1 = *(const uint32_t*)(krL + koff + 16);
                mma16816(acc[nt], aHi[ks], bh0, bh1);
                mma16816(acc[nt], aHi[ks], bl0, bl1);
                mma16816(acc[nt], aLo[ks], bh0, bh1);
            }
        }

        #pragma unroll
        for (int nt = 0; nt < 8; ++nt) {
            const int col0 = nt * 8 + qd * 2;
            const uint16_t mm = *(const uint16_t*)(cmaskA + col0);
            const bool m0 = (mm & 0xffu) != 0, m1 = (mm >> 8) != 0;
            float* c = acc[nt];
            float e0 = (rm0 || m0) ? EPSM : __expf(c[0] * 0.125f);
            float e1 = (rm0 || m1) ? EPSM : __expf(c[1] * 0.125f);
            float e2 = (rm1 || m0) ? EPSM : __expf(c[2] * 0.125f);
            float e3 = (rm1 || m1) ? EPSM : __expf(c[3] * 0.125f);
            lsum0 += e0 + e1;
            lsum1 += e2 + e3;
            float* dst = abase + (size_t)r0 * NSEQ + kt * KT + col0;
            *(float2*)dst              = make_float2(e0, e1);
            *(float2*)(dst + 8 * NSEQ) = make_float2(e2, e3);
        }
    }

    lsum0 += __shfl_xor_sync(0xffffffffu, lsum0, 1);
    lsum0 += __shfl_xor_sync(0xffffffffu, lsum0, 2);
    lsum1 += __shfl_xor_sync(0xffffffffu, lsum1, 1);
    lsum1 += __shfl_xor_sync(0xffffffffu, lsum1, 2);
    if (qd == 0) {
        g_l[bh * NSEQ + qt * 128 + r0]     = lsum0;
        g_l[bh * NSEQ + qt * 128 + r0 + 8] = lsum1;
    }
}

// ===========================================================================
// pv via mma.sync, pipelined: p = E/l (written back as attn), O = P.V via
// bf16 hi/lo split. CTA: 128 q-rows, 8 warps = 16 exclusive rows each.
// Chunk = 32 k. E fragments + V chunk register-prefetched one chunk ahead.
// V smem: word[kw][d] = pack2(bf16 V[2kw][d], bf16 V[2kw+1][d]), stride 72
// words -> B-fragment reads are single conflict-free LDS.32.
// ===========================================================================
#define PKT 32                          // k per chunk
#define VSTR 72                         // words per kw-row (64 + 8 pad)
#define PV_NW 16                        // kw rows per chunk (PKT/2)

__global__ void __launch_bounds__(256, 2)
pv_mma_kernel(const float* __restrict__ v, float* __restrict__ attn,
              float* __restrict__ out)
{
    __shared__ __align__(16) uint32_t vtHi[PV_NW * VSTR];   // 4608 B
    __shared__ __align__(16) uint32_t vtLo[PV_NW * VSTR];   // 4608 B

    const int tid  = threadIdx.x;
    const int lane = tid & 31, wid = tid >> 5;
    const int g = lane >> 2, qd = lane & 3;
    const int qt = blockIdx.x, bh = blockIdx.y;

    const int r0 = wid * 16 + g;                  // rows r0, r0+8 (warp-exclusive)
    const float rl0 = 1.f / g_l[bh * NSEQ + qt * 128 + r0];
    const float rl1 = 1.f / g_l[bh * NSEQ + qt * 128 + r0 + 8];

    float* abase = attn + ((size_t)bh * NSEQ + (size_t)qt * 128) * NSEQ;
    const float* vbase = v + (size_t)bh * NSEQ * DH;

    // V staging: thread owns k-pair p = tid>>4, d-slice d0 = (tid&15)*4
    const int vp = tid >> 4;
    const int d0 = (tid & 15) * 4;

    // ---- prefetch chunk 0 ----
    float4 vA, vB;
    float2 eReg[2][4];
    {
        const float* vb = vbase + (size_t)(2 * vp) * DH + d0;
        vA = *(const float4*)vb;
        vB = *(const float4*)(vb + DH);
        #pragma unroll
        for (int ks = 0; ks < 2; ++ks) {
            const float* ep = abase + (size_t)r0 * NSEQ + ks * 16 + qd * 2;
            eReg[ks][0] = *(const float2*)(ep);
            eReg[ks][1] = *(const float2*)(ep + 8 * NSEQ);
            eReg[ks][2] = *(const float2*)(ep + 8);
            eReg[ks][3] = *(const float2*)(ep + 8 * NSEQ + 8);
        }
    }

    float acc[8][4];
    #pragma unroll
    for (int nt = 0; nt < 8; ++nt)
        #pragma unroll
        for (int u = 0; u < 4; ++u) acc[nt][u] = 0.f;

    for (int kt = 0; kt < NSEQ / PKT; ++kt) {
        __syncthreads();   // prev MMA done with vt smem

        // ---- commit staged V: hi/lo k-pair words, transposed layout ----
        {
            float a4[4] = {vA.x, vA.y, vA.z, vA.w};
            float b4[4] = {vB.x, vB.y, vB.z, vB.w};
            uint32_t* hRow = vtHi + vp * VSTR + d0;
            uint32_t* lRow = vtLo + vp * VSTR + d0;
            #pragma unroll
            for (int e = 0; e < 4; ++e) {
                float ha = __bfloat162float(__float2bfloat16(a4[e]));
                float hb = __bfloat162float(__float2bfloat16(b4[e]));
                hRow[e] = pack2(ha, hb);
                lRow[e] = pack2(a4[e] - ha, b4[e] - hb);
            }
        }
        __syncthreads();

        // ---- build P fragments from this chunk's E; write P back to attn ----
        uint32_t pHi[2][4], pLo[2][4];
        #pragma unroll
        for (int ks = 0; ks < 2; ++ks) {
            float p0x = eReg[ks][0].x * rl0, p0y = eReg[ks][0].y * rl0;
            float p1x = eReg[ks][1].x * rl1, p1y = eReg[ks][1].y * rl1;
            float p2x = eReg[ks][2].x * rl0, p2y = eReg[ks][2].y * rl0;
            float p3x = eReg[ks][3].x * rl1, p3y = eReg[ks][3].y * rl1;
            float* pp = abase + (size_t)r0 * NSEQ + kt * PKT + ks * 16 + qd * 2;
            *(float2*)(pp)                = make_float2(p0x, p0y);
            *(float2*)(pp + 8 * NSEQ)     = make_float2(p1x, p1y);
            *(float2*)(pp + 8)            = make_float2(p2x, p2y);
            *(float2*)(pp + 8 * NSEQ + 8) = make_float2(p3x, p3y);
            float h, h2;
            h  = __bfloat162float(__float2bfloat16(p0x));
            h2 = __bfloat162float(__float2bfloat16(p0y));
            pHi[ks][0] = pack2(h, h2); pLo[ks][0] = pack2(p0x - h, p0y - h2);
            h  = __bfloat162float(__float2bfloat16(p1x));
            h2 = __bfloat162float(__float2bfloat16(p1y));
            pHi[ks][1] = pack2(h, h2); pLo[ks][1] = pack2(p1x - h, p1y - h2);
            h  = __bfloat162float(__float2bfloat16(p2x));
            h2 = __bfloat162float(__float2bfloat16(p2y));
            pHi[ks][2] = pack2(h, h2); pLo[ks][2] = pack2(p2x - h, p2y - h2);
            h  = __bfloat162float(__float2bfloat16(p3x));
            h2 = __bfloat162float(__float2bfloat16(p3y));
            pHi[ks][3] = pack2(h, h2); pLo[ks][3] = pack2(p3x - h, p3y - h2);
        }

        // ---- prefetch next chunk (E frags + V) — hidden behind MMAs below ----
        {
            const int nkt = (kt + 1 < NSEQ / PKT) ? kt + 1 : kt;
            const float* vb = vbase + (size_t)(nkt * PKT + 2 * vp) * DH + d0;
            vA = *(const float4*)vb;
            vB = *(const float4*)(vb + DH);
            #pragma unroll
            for (int ks = 0; ks < 2; ++ks) {
                const float* ep = abase + (size_t)r0 * NSEQ + nkt * PKT
                                + ks * 16 + qd * 2;
                eReg[ks][0] = *(const float2*)(ep);
                eReg[ks][1] = *(const float2*)(ep + 8 * NSEQ);
                eReg[ks][2] = *(const float2*)(ep + 8);
                eReg[ks][3] = *(const float2*)(ep + 8 * NSEQ + 8);
            }
        }

        // ---- MMA: 8 d-tiles x 2 k-steps x 3 products ----
        #pragma unroll
        for (int nt = 0; nt < 8; ++nt) {
            const int d = nt * 8 + g;
            #pragma unroll
            for (int ks = 0; ks < 2; ++ks) {
                const int kw0 = ks * 8 + qd;
                uint32_t bh0 = vtHi[kw0 * VSTR + d];
                uint32_t bh1 = vtHi[(kw0 + 4) * VSTR + d];
                uint32_t bl0 = vtLo[kw0 * VSTR + d];
                uint32_t bl1 = vtLo[(kw0 + 4) * VSTR + d];
                mma16816(acc[nt], pHi[ks], bh0, bh1);
                mma16816(acc[nt], pHi[ks], bl0, bl1);
                mma16816(acc[nt], pLo[ks], bh0, bh1);
            }
        }
    }

    // ---- O stores ----
    float* obase = out + ((size_t)bh * NSEQ + (size_t)qt * 128) * DH;
    #pragma unroll
    for (int nt = 0; nt < 8; ++nt) {
        float* op = obase + (size_t)r0 * DH + nt * 8 + qd * 2;
        *(float2*)op            = make_float2(acc[nt][0], acc[nt][1]);
        *(float2*)(op + 8 * DH) = make_float2(acc[nt][2], acc[nt][3]);
    }
}

extern "C" void kernel_launch(void* const* d_in, const int* in_sizes, int n_in,
                              void* d_out, int out_size)
{
    const float* q    = (const float*)d_in[0];
    const float* kmat = (const float*)d_in[1];
    const float* v    = (const float*)d_in[2];
    const int*   mask = (const int*)d_in[3];

    float* out  = (float*)d_out;                  // [B,H,N,D] first (tuple order)
    float* attn = out + (size_t)NBH * NSEQ * DH;  // [B,H,N,N] second

    qk_mma_kernel<<<dim3(NSEQ / 128, NBH), 256>>>(q, kmat, mask, attn);
    pv_mma_kernel<<<dim3(NSEQ / 128, NBH), 256>>>(v, attn, out);
}